// round 12
// baseline (speedup 1.0000x reference)
#include <cuda_runtime.h>
#include <cuda_fp16.h>
#include <math.h>
#include <stdint.h>

#define BN_ 4096
#define DN_ 512
#define KEFF 512
#define SHIFT 0.5f
#define TOTALB 2048

// ---------------- scratch (device globals; allocation-free kernel_launch) ----
__device__ __half g_Ah[(size_t)BN_ * KEFF]; // fnh (4 MB)
__device__ __half g_Bo[(size_t)BN_ * KEFF]; // foh (4 MB)
__device__ float g_pos[BN_];
__device__ float g_sum[2][BN_];             // per-row sumexp (shifted)
__device__ int   g_tgt[BN_];
__device__ unsigned g_done;                 // block completion counter

// ================= small PTX helpers (sm_100-safe) ===========================
__device__ __forceinline__ uint32_t smem_u32(const void* p) {
    uint32_t a;
    asm("{ .reg .u64 t; cvta.to.shared.u64 t, %1; cvt.u32.u64 %0, t; }"
        : "=r"(a) : "l"(p));
    return a;
}
__device__ __forceinline__ void cp16(uint32_t dst, const void* src) {
    asm volatile("cp.async.cg.shared.global [%0], [%1], 16;" :: "r"(dst), "l"(src));
}
#define CP_COMMIT() asm volatile("cp.async.commit_group;" ::: "memory")
#define CP_WAIT(n)  asm volatile("cp.async.wait_group %0;" :: "n"(n) : "memory")

__device__ __forceinline__ void ldsm_x4(uint32_t* r, uint32_t addr) {
    asm volatile("ldmatrix.sync.aligned.m8n8.x4.shared.b16 {%0,%1,%2,%3}, [%4];"
                 : "=r"(r[0]), "=r"(r[1]), "=r"(r[2]), "=r"(r[3]) : "r"(addr));
}
__device__ __forceinline__ void mma16816(float* c, const uint32_t* a, const uint32_t* b) {
    asm volatile(
        "mma.sync.aligned.m16n8k16.row.col.f32.f16.f16.f32 "
        "{%0,%1,%2,%3}, {%4,%5,%6,%7}, {%8,%9}, {%0,%1,%2,%3};"
        : "+f"(c[0]), "+f"(c[1]), "+f"(c[2]), "+f"(c[3])
        : "r"(a[0]), "r"(a[1]), "r"(a[2]), "r"(a[3]), "r"(b[0]), "r"(b[1]));
}

// ------- prep: blocks 0..4095 normalize+cast+pos; block 4096 does targets ----
__global__ void prep_k(const float* __restrict__ feat,
                       const float* __restrict__ feat_old,
                       const int* __restrict__ tgt_raw) {
    int row = blockIdx.x;
    if (row == BN_) {
        __shared__ int s_any;
        if (threadIdx.x == 0) { s_any = 0; g_done = 0u; }
        __syncthreads();
        int local = 0;
        for (int j = threadIdx.x; j < BN_; j += 128)
            if ((j & 1) && tgt_raw[j] != 0) local = 1;
        if (local) atomicOr(&s_any, 1);
        __syncthreads();
        int is64 = (s_any == 0);
        for (int j = threadIdx.x; j < BN_; j += 128) {
            g_tgt[j] = is64 ? tgt_raw[2 * j] : tgt_raw[j];
            g_sum[0][j] = 0.f;
            g_sum[1][j] = 0.f;
        }
        return;
    }

    const float* a = feat + (size_t)row * DN_;
    const float* b = feat_old + (size_t)row * DN_;

    float snn = 0.f, soo = 0.f, sno = 0.f;
    for (int j = threadIdx.x; j < DN_; j += 128) {
        float x = a[j], y = b[j];
        snn += x * x; soo += y * y; sno += x * y;
    }
    #pragma unroll
    for (int o = 16; o; o >>= 1) {
        snn += __shfl_xor_sync(0xffffffffu, snn, o);
        soo += __shfl_xor_sync(0xffffffffu, soo, o);
        sno += __shfl_xor_sync(0xffffffffu, sno, o);
    }
    __shared__ float red[3][4];
    int w = threadIdx.x >> 5, l = threadIdx.x & 31;
    if (l == 0) { red[0][w] = snn; red[1][w] = soo; red[2][w] = sno; }
    __syncthreads();
    float tn = red[0][0] + red[0][1] + red[0][2] + red[0][3];
    float to = red[1][0] + red[1][1] + red[1][2] + red[1][3];
    float tx = red[2][0] + red[2][1] + red[2][2] + red[2][3];
    float invn = 1.f / fmaxf(sqrtf(tn), 1e-12f);
    float invo = 1.f / fmaxf(sqrtf(to), 1e-12f);
    if (threadIdx.x == 0) g_pos[row] = tx * invn * invo;

    __half* An = g_Ah + (size_t)row * KEFF;
    __half* Bo = g_Bo + (size_t)row * KEFF;
    for (int j = threadIdx.x; j < DN_; j += 128) {
        An[j] = __float2half_rn(a[j] * invn);
        Bo[j] = __float2half_rn(b[j] * invo);
    }
}

// == fused fp16 GEMM (R9 geometry) + exp row-sum + last-block finalize ========
// CTA 128x128, 256 thr, warp grid 2x4 (warp tile 64x32), KC=32, 4-stage.
#define KC 32
#define NITER (KEFF / KC)          // 16
#define ROWB 80
#define ATILE (128 * ROWB)         // 10240
#define STAGEB (2 * ATILE)         // 20480
#define GEMM_SMEM 81920

__global__ void __launch_bounds__(256, 2) gemm_mma_k(float* __restrict__ out) {
    int mat = blockIdx.z;
    int bx = blockIdx.x, by = blockIdx.y;
    extern __shared__ char sm[];
    int tid = threadIdx.x, wid = tid >> 5, lane = tid & 31;
    bool skip = (mat == 1) && (bx < by);      // symmetry: only upper triangle

    if (!skip) {
        uint32_t sbase = smem_u32(sm);
        int warpM = wid >> 2, warpN = wid & 3;
        const __half* Ag = g_Ah;
        const __half* Bg = mat ? g_Ah : g_Bo;
        int row0 = by * 128, col0 = bx * 128;

        int rA0 = tid >> 2, gA0 = tid & 3, rA1 = (tid + 256) >> 2;
        const char* pA0 = (const char*)(Ag + (size_t)(row0 + rA0) * KEFF) + gA0 * 16;
        const char* pA1 = (const char*)(Ag + (size_t)(row0 + rA1) * KEFF) + gA0 * 16;
        const char* pB0 = (const char*)(Bg + (size_t)(col0 + rA0) * KEFF) + gA0 * 16;
        const char* pB1 = (const char*)(Bg + (size_t)(col0 + rA1) * KEFF) + gA0 * 16;
        uint32_t dA0 = rA0 * ROWB + gA0 * 16, dA1 = rA1 * ROWB + gA0 * 16;
        uint32_t dB0 = ATILE + dA0, dB1 = ATILE + dA1;

        #define ISSUE(it) do {                                                 \
            uint32_t st = sbase + ((it) & 3) * STAGEB;                         \
            int ko = (it) * 64;                                                \
            cp16(st + dA0, pA0 + ko); cp16(st + dA1, pA1 + ko);                \
            cp16(st + dB0, pB0 + ko); cp16(st + dB1, pB1 + ko);                \
        } while (0)

        ISSUE(0); CP_COMMIT();
        ISSUE(1); CP_COMMIT();
        ISSUE(2); CP_COMMIT();

        float acc[4][4][4] = {};
        uint32_t aoff = (uint32_t)((warpM * 64 + (lane & 15)) * ROWB + (lane >> 4) * 16);
        uint32_t boff = (uint32_t)(ATILE +
            (warpN * 32 + (lane & 7) + (lane >> 4) * 8) * ROWB + ((lane >> 3) & 1) * 16);

        for (int it = 0; it < NITER; it++) {
            CP_WAIT(2);
            __syncthreads();
            if (it + 3 < NITER) ISSUE(it + 3);
            CP_COMMIT();

            uint32_t st = sbase + (it & 3) * STAGEB;
            uint32_t ab = st + aoff, bb = st + boff;
            #pragma unroll
            for (int kk = 0; kk < 2; kk++) {
                uint32_t af[4][4], bf[2][4];
                #pragma unroll
                for (int mt = 0; mt < 4; mt++)
                    ldsm_x4(af[mt], ab + kk * 32 + mt * (16 * ROWB));
                ldsm_x4(bf[0], bb + kk * 32);
                ldsm_x4(bf[1], bb + kk * 32 + 16 * ROWB);
                #pragma unroll
                for (int mt = 0; mt < 4; mt++)
                    #pragma unroll
                    for (int nt = 0; nt < 4; nt++)
                        mma16816(acc[mt][nt], af[mt], &bf[nt >> 1][(nt & 1) * 2]);
            }
        }

        CP_WAIT(0);
        __syncthreads();

        // ---- epilogue: masked exp, accumulate row (and sym col) sums ----
        float* srow = (float*)sm;                 // [128]
        float* scol = (float*)(sm + 512);         // [128]
        int* tjs = (int*)(sm + 1024);             // [128]
        if (tid < 128) {
            srow[tid] = 0.f;
            scol[tid] = 0.f;
            tjs[tid] = g_tgt[col0 + tid];
        }
        __syncthreads();

        bool sym = (mat == 1) && (bx > by);

        #pragma unroll
        for (int mt = 0; mt < 4; mt++) {
            int rl0 = warpM * 64 + mt * 16 + (lane >> 2);
            int ti0 = g_tgt[row0 + rl0], ti1 = g_tgt[row0 + rl0 + 8];
            #pragma unroll
            for (int nt = 0; nt < 4; nt++) {
                int cl = warpN * 32 + nt * 8 + (lane & 3) * 2;
                int tj0 = tjs[cl], tj1 = tjs[cl + 1];
                acc[mt][nt][0] = (ti0 == tj0) ? 0.f : __expf(100.f * (acc[mt][nt][0] - SHIFT));
                acc[mt][nt][1] = (ti0 == tj1) ? 0.f : __expf(100.f * (acc[mt][nt][1] - SHIFT));
                acc[mt][nt][2] = (ti1 == tj0) ? 0.f : __expf(100.f * (acc[mt][nt][2] - SHIFT));
                acc[mt][nt][3] = (ti1 == tj1) ? 0.f : __expf(100.f * (acc[mt][nt][3] - SHIFT));
            }
            float s0 = 0.f, s1 = 0.f;
            #pragma unroll
            for (int nt = 0; nt < 4; nt++) {
                s0 += acc[mt][nt][0] + acc[mt][nt][1];
                s1 += acc[mt][nt][2] + acc[mt][nt][3];
            }
            atomicAdd(&srow[rl0], s0);
            atomicAdd(&srow[rl0 + 8], s1);
        }
        if (sym) {
            #pragma unroll
            for (int nt = 0; nt < 4; nt++) {
                int cl = warpN * 32 + nt * 8 + (lane & 3) * 2;
                float c0 = 0.f, c1 = 0.f;
                #pragma unroll
                for (int mt = 0; mt < 4; mt++) {
                    c0 += acc[mt][nt][0] + acc[mt][nt][2];
                    c1 += acc[mt][nt][1] + acc[mt][nt][3];
                }
                atomicAdd(&scol[cl], c0);
                atomicAdd(&scol[cl + 1], c1);
            }
        }
        __syncthreads();

        if (tid < 128) {
            atomicAdd(&g_sum[mat][row0 + tid], srow[tid]);
            if (sym) atomicAdd(&g_sum[1][col0 + tid], scol[tid]);
        }
        #undef ISSUE
    }

    // ---- completion counting; last block computes the final loss ----
    __threadfence();
    __shared__ unsigned s_rank;
    __syncthreads();
    if (tid == 0) s_rank = atomicAdd(&g_done, 1u);
    __syncthreads();
    if (s_rank == TOTALB - 1) {
        __threadfence();
        float s = 0.f;
        for (int j = tid; j < BN_; j += 256) {
            float pos = g_pos[j];
            float tot = __expf(100.f * (pos - SHIFT)) + g_sum[0][j] + g_sum[1][j];
            s += logf(tot) + 100.f * SHIFT - 100.f * pos;
        }
        #pragma unroll
        for (int o = 16; o; o >>= 1) s += __shfl_xor_sync(0xffffffffu, s, o);
        float* red = (float*)sm;
        __syncthreads();
        if (lane == 0) red[wid] = s;
        __syncthreads();
        if (wid == 0) {
            float t = (lane < 8) ? red[lane] : 0.f;
            #pragma unroll
            for (int o = 4; o; o >>= 1) t += __shfl_xor_sync(0xffffffffu, t, o);
            if (lane == 0) {
                out[0] = t * (1.0f / (float)BN_);
                g_done = 0u;           // reset for next graph replay
            }
        }
    }
}

// ---------------- launch ------------------------------------------------------
extern "C" void kernel_launch(void* const* d_in, const int* in_sizes, int n_in,
                              void* d_out, int out_size) {
    const float* feat     = (const float*)d_in[0];
    const float* feat_old = (const float*)d_in[1];
    const int*   tgt_raw  = (const int*)d_in[2];
    float* out = (float*)d_out;

    cudaFuncSetAttribute(gemm_mma_k, cudaFuncAttributeMaxDynamicSharedMemorySize,
                         GEMM_SMEM);

    prep_k<<<BN_ + 1, 128>>>(feat, feat_old, tgt_raw);
    dim3 grid(32, 32, 2);
    gemm_mma_k<<<grid, 256, GEMM_SMEM>>>(out);
}

// round 13
// speedup vs baseline: 1.0307x; 1.0307x over previous
#include <cuda_runtime.h>
#include <cuda_fp16.h>
#include <math.h>
#include <stdint.h>

#define BN_ 4096
#define DN_ 512
#define KEFF 512
#define SHIFT 0.5f
#define TOTALB 2048

// ---------------- scratch (device globals; allocation-free kernel_launch) ----
__device__ __half g_Ah[(size_t)BN_ * KEFF]; // fnh (4 MB)
__device__ __half g_Bo[(size_t)BN_ * KEFF]; // foh (4 MB)
__device__ float g_pos[BN_];
__device__ float g_sum[2][BN_];             // per-row sumexp (shifted)
__device__ int   g_tgt[BN_];
__device__ unsigned g_done;                 // block completion counter

// ================= small PTX helpers (sm_100-safe) ===========================
__device__ __forceinline__ uint32_t smem_u32(const void* p) {
    uint32_t a;
    asm("{ .reg .u64 t; cvta.to.shared.u64 t, %1; cvt.u32.u64 %0, t; }"
        : "=r"(a) : "l"(p));
    return a;
}
__device__ __forceinline__ void cp16(uint32_t dst, const void* src) {
    asm volatile("cp.async.cg.shared.global [%0], [%1], 16;" :: "r"(dst), "l"(src));
}
#define CP_COMMIT() asm volatile("cp.async.commit_group;" ::: "memory")
#define CP_WAIT(n)  asm volatile("cp.async.wait_group %0;" :: "n"(n) : "memory")

__device__ __forceinline__ void ldsm_x4(uint32_t* r, uint32_t addr) {
    asm volatile("ldmatrix.sync.aligned.m8n8.x4.shared.b16 {%0,%1,%2,%3}, [%4];"
                 : "=r"(r[0]), "=r"(r[1]), "=r"(r[2]), "=r"(r[3]) : "r"(addr));
}
__device__ __forceinline__ void mma16816(float* c, const uint32_t* a, const uint32_t* b) {
    asm volatile(
        "mma.sync.aligned.m16n8k16.row.col.f32.f16.f16.f32 "
        "{%0,%1,%2,%3}, {%4,%5,%6,%7}, {%8,%9}, {%0,%1,%2,%3};"
        : "+f"(c[0]), "+f"(c[1]), "+f"(c[2]), "+f"(c[3])
        : "r"(a[0]), "r"(a[1]), "r"(a[2]), "r"(a[3]), "r"(b[0]), "r"(b[1]));
}

// ------- prep: blocks 0..4095 normalize+cast+pos; block 4096 does targets ----
__global__ void prep_k(const float* __restrict__ feat,
                       const float* __restrict__ feat_old,
                       const int* __restrict__ tgt_raw) {
    int row = blockIdx.x;
    if (row == BN_) {
        __shared__ int s_any;
        if (threadIdx.x == 0) { s_any = 0; g_done = 0u; }
        __syncthreads();
        int local = 0;
        for (int j = threadIdx.x; j < BN_; j += 128)
            if ((j & 1) && tgt_raw[j] != 0) local = 1;
        if (local) atomicOr(&s_any, 1);
        __syncthreads();
        int is64 = (s_any == 0);
        for (int j = threadIdx.x; j < BN_; j += 128) {
            g_tgt[j] = is64 ? tgt_raw[2 * j] : tgt_raw[j];
            g_sum[0][j] = 0.f;
            g_sum[1][j] = 0.f;
        }
        return;
    }

    const float* a = feat + (size_t)row * DN_;
    const float* b = feat_old + (size_t)row * DN_;

    float snn = 0.f, soo = 0.f, sno = 0.f;
    for (int j = threadIdx.x; j < DN_; j += 128) {
        float x = a[j], y = b[j];
        snn += x * x; soo += y * y; sno += x * y;
    }
    #pragma unroll
    for (int o = 16; o; o >>= 1) {
        snn += __shfl_xor_sync(0xffffffffu, snn, o);
        soo += __shfl_xor_sync(0xffffffffu, soo, o);
        sno += __shfl_xor_sync(0xffffffffu, sno, o);
    }
    __shared__ float red[3][4];
    int w = threadIdx.x >> 5, l = threadIdx.x & 31;
    if (l == 0) { red[0][w] = snn; red[1][w] = soo; red[2][w] = sno; }
    __syncthreads();
    float tn = red[0][0] + red[0][1] + red[0][2] + red[0][3];
    float to = red[1][0] + red[1][1] + red[1][2] + red[1][3];
    float tx = red[2][0] + red[2][1] + red[2][2] + red[2][3];
    float invn = 1.f / fmaxf(sqrtf(tn), 1e-12f);
    float invo = 1.f / fmaxf(sqrtf(to), 1e-12f);
    if (threadIdx.x == 0) g_pos[row] = tx * invn * invo;

    __half* An = g_Ah + (size_t)row * KEFF;
    __half* Bo = g_Bo + (size_t)row * KEFF;
    for (int j = threadIdx.x; j < DN_; j += 128) {
        An[j] = __float2half_rn(a[j] * invn);
        Bo[j] = __float2half_rn(b[j] * invo);
    }
}

// == fused fp16 GEMM (R10 geometry verbatim) + exp row-sum + finalize =========
// CTA 128x128, 512 thr, warp grid 4x4 (warp tile 32x32), KC=32, 4-stage.
#define KC 32
#define NITER (KEFF / KC)          // 16
#define ROWB 80
#define ATILE (128 * ROWB)         // 10240
#define STAGEB (2 * ATILE)         // 20480
#define GEMM_SMEM 81920

__global__ void __launch_bounds__(512, 2) gemm_mma_k(float* __restrict__ out) {
    int mat = blockIdx.z;
    int bx = blockIdx.x, by = blockIdx.y;
    extern __shared__ char sm[];
    int tid = threadIdx.x, wid = tid >> 5, lane = tid & 31;
    bool skip = (mat == 1) && (bx < by);      // symmetry: only upper triangle

    if (!skip) {
        uint32_t sbase = smem_u32(sm);
        int warpM = wid >> 2, warpN = wid & 3;    // 4x4 warps, 32x32 each
        const __half* Ag = g_Ah;
        const __half* Bg = mat ? g_Ah : g_Bo;
        int row0 = by * 128, col0 = bx * 128;

        int r = tid >> 2, g = tid & 3;
        const char* pA = (const char*)(Ag + (size_t)(row0 + r) * KEFF) + g * 16;
        const char* pB = (const char*)(Bg + (size_t)(col0 + r) * KEFF) + g * 16;
        uint32_t dA = r * ROWB + g * 16;
        uint32_t dB = ATILE + dA;

        #define ISSUE(it) do {                                                 \
            uint32_t st = sbase + ((it) & 3) * STAGEB;                         \
            int ko = (it) * 64;                                                \
            cp16(st + dA, pA + ko); cp16(st + dB, pB + ko);                    \
        } while (0)

        ISSUE(0); CP_COMMIT();
        ISSUE(1); CP_COMMIT();
        ISSUE(2); CP_COMMIT();

        float acc[2][4][4] = {};
        uint32_t aoff = (uint32_t)((warpM * 32 + (lane & 15)) * ROWB + (lane >> 4) * 16);
        uint32_t boff = (uint32_t)(ATILE +
            (warpN * 32 + (lane & 7) + (lane >> 4) * 8) * ROWB + ((lane >> 3) & 1) * 16);

        for (int it = 0; it < NITER; it++) {
            CP_WAIT(2);
            __syncthreads();
            if (it + 3 < NITER) ISSUE(it + 3);
            CP_COMMIT();

            uint32_t st = sbase + (it & 3) * STAGEB;
            uint32_t ab = st + aoff, bb = st + boff;
            #pragma unroll
            for (int kk = 0; kk < 2; kk++) {
                uint32_t af[2][4], bf[2][4];
                ldsm_x4(af[0], ab + kk * 32);
                ldsm_x4(af[1], ab + kk * 32 + 16 * ROWB);
                ldsm_x4(bf[0], bb + kk * 32);
                ldsm_x4(bf[1], bb + kk * 32 + 16 * ROWB);
                #pragma unroll
                for (int mt = 0; mt < 2; mt++)
                    #pragma unroll
                    for (int nt = 0; nt < 4; nt++)
                        mma16816(acc[mt][nt], af[mt], &bf[nt >> 1][(nt & 1) * 2]);
            }
        }

        CP_WAIT(0);
        __syncthreads();

        // ---- epilogue: masked exp, accumulate row (and sym col) sums ----
        float* srow = (float*)sm;                 // [128]
        float* scol = (float*)(sm + 512);         // [128]
        int* tjs = (int*)(sm + 1024);             // [128]
        if (tid < 128) {
            srow[tid] = 0.f;
            scol[tid] = 0.f;
            tjs[tid] = g_tgt[col0 + tid];
        }
        __syncthreads();

        bool sym = (mat == 1) && (bx > by);

        #pragma unroll
        for (int mt = 0; mt < 2; mt++) {
            int rl0 = warpM * 32 + mt * 16 + (lane >> 2);
            int ti0 = g_tgt[row0 + rl0], ti1 = g_tgt[row0 + rl0 + 8];
            #pragma unroll
            for (int nt = 0; nt < 4; nt++) {
                int cl = warpN * 32 + nt * 8 + (lane & 3) * 2;
                int tj0 = tjs[cl], tj1 = tjs[cl + 1];
                acc[mt][nt][0] = (ti0 == tj0) ? 0.f : __expf(100.f * (acc[mt][nt][0] - SHIFT));
                acc[mt][nt][1] = (ti0 == tj1) ? 0.f : __expf(100.f * (acc[mt][nt][1] - SHIFT));
                acc[mt][nt][2] = (ti1 == tj0) ? 0.f : __expf(100.f * (acc[mt][nt][2] - SHIFT));
                acc[mt][nt][3] = (ti1 == tj1) ? 0.f : __expf(100.f * (acc[mt][nt][3] - SHIFT));
            }
            float s0 = 0.f, s1 = 0.f;
            #pragma unroll
            for (int nt = 0; nt < 4; nt++) {
                s0 += acc[mt][nt][0] + acc[mt][nt][1];
                s1 += acc[mt][nt][2] + acc[mt][nt][3];
            }
            atomicAdd(&srow[rl0], s0);
            atomicAdd(&srow[rl0 + 8], s1);
        }
        if (sym) {
            #pragma unroll
            for (int nt = 0; nt < 4; nt++) {
                int cl = warpN * 32 + nt * 8 + (lane & 3) * 2;
                float c0 = 0.f, c1 = 0.f;
                #pragma unroll
                for (int mt = 0; mt < 2; mt++) {
                    c0 += acc[mt][nt][0] + acc[mt][nt][2];
                    c1 += acc[mt][nt][1] + acc[mt][nt][3];
                }
                atomicAdd(&scol[cl], c0);
                atomicAdd(&scol[cl + 1], c1);
            }
        }
        __syncthreads();

        if (tid < 128) {
            atomicAdd(&g_sum[mat][row0 + tid], srow[tid]);
            if (sym) atomicAdd(&g_sum[1][col0 + tid], scol[tid]);
        }
        #undef ISSUE
    }

    // ---- completion counting; last block computes the final loss ----
    __threadfence();
    __shared__ unsigned s_rank;
    __syncthreads();
    if (tid == 0) s_rank = atomicAdd(&g_done, 1u);
    __syncthreads();
    if (s_rank == TOTALB - 1) {
        __threadfence();
        float s = 0.f;
        for (int j = tid; j < BN_; j += 512) {
            float pos = g_pos[j];
            float tot = __expf(100.f * (pos - SHIFT)) + g_sum[0][j] + g_sum[1][j];
            s += logf(tot) + 100.f * SHIFT - 100.f * pos;
        }
        #pragma unroll
        for (int o = 16; o; o >>= 1) s += __shfl_xor_sync(0xffffffffu, s, o);
        float* red = (float*)sm;
        __syncthreads();
        if (lane == 0) red[wid] = s;
        __syncthreads();
        if (wid == 0) {
            float t = (lane < 16) ? red[lane] : 0.f;
            #pragma unroll
            for (int o = 8; o; o >>= 1) t += __shfl_xor_sync(0xffffffffu, t, o);
            if (lane == 0) {
                out[0] = t * (1.0f / (float)BN_);
                g_done = 0u;           // reset for next graph replay
            }
        }
    }
}

// ---------------- launch ------------------------------------------------------
extern "C" void kernel_launch(void* const* d_in, const int* in_sizes, int n_in,
                              void* d_out, int out_size) {
    const float* feat     = (const float*)d_in[0];
    const float* feat_old = (const float*)d_in[1];
    const int*   tgt_raw  = (const int*)d_in[2];
    float* out = (float*)d_out;

    cudaFuncSetAttribute(gemm_mma_k, cudaFuncAttributeMaxDynamicSharedMemorySize,
                         GEMM_SMEM);

    prep_k<<<BN_ + 1, 128>>>(feat, feat_old, tgt_raw);
    dim3 grid(32, 32, 2);
    gemm_mma_k<<<grid, 512, GEMM_SMEM>>>(out);
}

// round 14
// speedup vs baseline: 1.1724x; 1.1376x over previous
#include <cuda_runtime.h>
#include <cuda_fp16.h>
#include <math.h>
#include <stdint.h>

#define BN_ 4096
#define DN_ 512
#define KEFF 512
#define SHIFT 0.5f

// ---------------- scratch (device globals; allocation-free kernel_launch) ----
__device__ __half g_Ah[(size_t)BN_ * KEFF]; // fnh (4 MB)
__device__ __half g_Bo[(size_t)BN_ * KEFF]; // foh (4 MB)
__device__ float g_pos[BN_];
__device__ float g_sum[2][BN_];             // per-row sumexp (shifted)
__device__ int   g_tgt[BN_];

// ================= small PTX helpers (sm_100-safe) ===========================
__device__ __forceinline__ uint32_t smem_u32(const void* p) {
    uint32_t a;
    asm("{ .reg .u64 t; cvta.to.shared.u64 t, %1; cvt.u32.u64 %0, t; }"
        : "=r"(a) : "l"(p));
    return a;
}
__device__ __forceinline__ void cp16(uint32_t dst, const void* src) {
    asm volatile("cp.async.cg.shared.global [%0], [%1], 16;" :: "r"(dst), "l"(src));
}
#define CP_COMMIT() asm volatile("cp.async.commit_group;" ::: "memory")
#define CP_WAIT(n)  asm volatile("cp.async.wait_group %0;" :: "n"(n) : "memory")

__device__ __forceinline__ void ldsm_x4(uint32_t* r, uint32_t addr) {
    asm volatile("ldmatrix.sync.aligned.m8n8.x4.shared.b16 {%0,%1,%2,%3}, [%4];"
                 : "=r"(r[0]), "=r"(r[1]), "=r"(r[2]), "=r"(r[3]) : "r"(addr));
}
__device__ __forceinline__ void mma16816(float* c, const uint32_t* a, const uint32_t* b) {
    asm volatile(
        "mma.sync.aligned.m16n8k16.row.col.f32.f16.f16.f32 "
        "{%0,%1,%2,%3}, {%4,%5,%6,%7}, {%8,%9}, {%0,%1,%2,%3};"
        : "+f"(c[0]), "+f"(c[1]), "+f"(c[2]), "+f"(c[3])
        : "r"(a[0]), "r"(a[1]), "r"(a[2]), "r"(a[3]), "r"(b[0]), "r"(b[1]));
}

// ------- prep: blocks 0..4095 normalize+cast+pos; block 4096 does targets ----
__global__ void prep_k(const float* __restrict__ feat,
                       const float* __restrict__ feat_old,
                       const int* __restrict__ tgt_raw) {
    int row = blockIdx.x;
    if (row == BN_) {
        __shared__ int s_any;
        if (threadIdx.x == 0) s_any = 0;
        __syncthreads();
        int local = 0;
        for (int j = threadIdx.x; j < BN_; j += 128)
            if ((j & 1) && tgt_raw[j] != 0) local = 1;
        if (local) atomicOr(&s_any, 1);
        __syncthreads();
        int is64 = (s_any == 0);
        for (int j = threadIdx.x; j < BN_; j += 128) {
            g_tgt[j] = is64 ? tgt_raw[2 * j] : tgt_raw[j];
            g_sum[0][j] = 0.f;
            g_sum[1][j] = 0.f;
        }
        return;
    }

    const float* a = feat + (size_t)row * DN_;
    const float* b = feat_old + (size_t)row * DN_;

    float snn = 0.f, soo = 0.f, sno = 0.f;
    for (int j = threadIdx.x; j < DN_; j += 128) {
        float x = a[j], y = b[j];
        snn += x * x; soo += y * y; sno += x * y;
    }
    #pragma unroll
    for (int o = 16; o; o >>= 1) {
        snn += __shfl_xor_sync(0xffffffffu, snn, o);
        soo += __shfl_xor_sync(0xffffffffu, soo, o);
        sno += __shfl_xor_sync(0xffffffffu, sno, o);
    }
    __shared__ float red[3][4];
    int w = threadIdx.x >> 5, l = threadIdx.x & 31;
    if (l == 0) { red[0][w] = snn; red[1][w] = soo; red[2][w] = sno; }
    __syncthreads();
    float tn = red[0][0] + red[0][1] + red[0][2] + red[0][3];
    float to = red[1][0] + red[1][1] + red[1][2] + red[1][3];
    float tx = red[2][0] + red[2][1] + red[2][2] + red[2][3];
    float invn = 1.f / fmaxf(sqrtf(tn), 1e-12f);
    float invo = 1.f / fmaxf(sqrtf(to), 1e-12f);
    if (threadIdx.x == 0) g_pos[row] = tx * invn * invo;

    __half* An = g_Ah + (size_t)row * KEFF;
    __half* Bo = g_Bo + (size_t)row * KEFF;
    for (int j = threadIdx.x; j < DN_; j += 128) {
        An[j] = __float2half_rn(a[j] * invn);
        Bo[j] = __float2half_rn(b[j] * invo);
    }
}

// == fp16 GEMM + masked exp row-sum; 512 thr, 32x32 warp tile, KC=64, 3-stage ==
#define KC 64
#define NITER (KEFF / KC)          // 8
#define ROWB 144                   // 128B data + 16B pad (conflict-free ldsm)
#define ATILE (128 * ROWB)         // 18432
#define STAGEB (2 * ATILE)         // 36864
#define GEMM_SMEM (3 * STAGEB)     // 110592

__global__ void __launch_bounds__(512, 2) gemm_mma_k() {
    int mat = blockIdx.z;
    int bx = blockIdx.x, by = blockIdx.y;
    if (mat == 1 && bx < by) return;          // symmetry: only upper triangle

    extern __shared__ char sm[];
    uint32_t sbase = smem_u32(sm);
    int tid = threadIdx.x, wid = tid >> 5, lane = tid & 31;
    int warpM = wid >> 2, warpN = wid & 3;    // 4x4 warps, 32x32 each
    const __half* Ag = g_Ah;
    const __half* Bg = mat ? g_Ah : g_Bo;
    int row0 = by * 128, col0 = bx * 128;

    // cp.async: 2048 segs/stage (16B each); 4 per thread
    uint32_t dseg[4];
    const char* pseg[4];
    #pragma unroll
    for (int k = 0; k < 4; k++) {
        int s = tid + k * 512;
        int isB = s >= 1024;
        int r = (s - (isB ? 1024 : 0)) >> 3;
        int sc = s & 7;
        const __half* base = isB ? Bg : Ag;
        int gr = (isB ? col0 : row0) + r;
        pseg[k] = (const char*)(base + (size_t)gr * KEFF) + sc * 16;
        dseg[k] = (isB ? ATILE : 0) + r * ROWB + sc * 16;
    }

    #define ISSUE(it) do {                                                     \
        uint32_t st = sbase + ((it) % 3) * STAGEB;                             \
        int ko = (it) * 128;                                                   \
        cp16(st + dseg[0], pseg[0] + ko); cp16(st + dseg[1], pseg[1] + ko);    \
        cp16(st + dseg[2], pseg[2] + ko); cp16(st + dseg[3], pseg[3] + ko);    \
    } while (0)

    ISSUE(0); CP_COMMIT();
    ISSUE(1); CP_COMMIT();

    float acc[2][4][4] = {};
    uint32_t aoff = (uint32_t)((warpM * 32 + (lane & 15)) * ROWB + (lane >> 4) * 16);
    uint32_t boff = (uint32_t)(ATILE +
        (warpN * 32 + (lane & 7) + (lane >> 4) * 8) * ROWB + ((lane >> 3) & 1) * 16);

    for (int it = 0; it < NITER; it++) {
        CP_WAIT(1);
        __syncthreads();
        if (it + 2 < NITER) ISSUE(it + 2);
        CP_COMMIT();

        uint32_t st = sbase + (it % 3) * STAGEB;
        uint32_t ab = st + aoff, bb = st + boff;
        #pragma unroll
        for (int kk = 0; kk < 4; kk++) {
            uint32_t af[2][4], bf[2][4];
            ldsm_x4(af[0], ab + kk * 32);
            ldsm_x4(af[1], ab + kk * 32 + 16 * ROWB);
            ldsm_x4(bf[0], bb + kk * 32);
            ldsm_x4(bf[1], bb + kk * 32 + 16 * ROWB);
            #pragma unroll
            for (int mt = 0; mt < 2; mt++)
                #pragma unroll
                for (int nt = 0; nt < 4; nt++)
                    mma16816(acc[mt][nt], af[mt], &bf[nt >> 1][(nt & 1) * 2]);
        }
    }

    CP_WAIT(0);
    __syncthreads();

    // ---- epilogue: masked exp, accumulate row (and sym col) sums ----
    float* srow = (float*)sm;                 // [128]
    float* scol = (float*)(sm + 512);         // [128]
    int* tjs = (int*)(sm + 1024);             // [128]
    if (tid < 128) {
        srow[tid] = 0.f;
        scol[tid] = 0.f;
        tjs[tid] = g_tgt[col0 + tid];
    }
    __syncthreads();

    bool sym = (mat == 1) && (bx > by);

    #pragma unroll
    for (int mt = 0; mt < 2; mt++) {
        int rl0 = warpM * 32 + mt * 16 + (lane >> 2);
        int ti0 = g_tgt[row0 + rl0], ti1 = g_tgt[row0 + rl0 + 8];
        #pragma unroll
        for (int nt = 0; nt < 4; nt++) {
            int cl = warpN * 32 + nt * 8 + (lane & 3) * 2;
            int tj0 = tjs[cl], tj1 = tjs[cl + 1];
            acc[mt][nt][0] = (ti0 == tj0) ? 0.f : __expf(100.f * (acc[mt][nt][0] - SHIFT));
            acc[mt][nt][1] = (ti0 == tj1) ? 0.f : __expf(100.f * (acc[mt][nt][1] - SHIFT));
            acc[mt][nt][2] = (ti1 == tj0) ? 0.f : __expf(100.f * (acc[mt][nt][2] - SHIFT));
            acc[mt][nt][3] = (ti1 == tj1) ? 0.f : __expf(100.f * (acc[mt][nt][3] - SHIFT));
        }
        float s0 = 0.f, s1 = 0.f;
        #pragma unroll
        for (int nt = 0; nt < 4; nt++) {
            s0 += acc[mt][nt][0] + acc[mt][nt][1];
            s1 += acc[mt][nt][2] + acc[mt][nt][3];
        }
        atomicAdd(&srow[rl0], s0);
        atomicAdd(&srow[rl0 + 8], s1);
    }
    if (sym) {
        #pragma unroll
        for (int nt = 0; nt < 4; nt++) {
            int cl = warpN * 32 + nt * 8 + (lane & 3) * 2;
            float c0 = 0.f, c1 = 0.f;
            #pragma unroll
            for (int mt = 0; mt < 2; mt++) {
                c0 += acc[mt][nt][0] + acc[mt][nt][2];
                c1 += acc[mt][nt][1] + acc[mt][nt][3];
            }
            atomicAdd(&scol[cl], c0);
            atomicAdd(&scol[cl + 1], c1);
        }
    }
    __syncthreads();

    if (tid < 128) {
        atomicAdd(&g_sum[mat][row0 + tid], srow[tid]);
        if (sym) atomicAdd(&g_sum[1][col0 + tid], scol[tid]);
    }
    #undef ISSUE
}

// ---------------- finalize: per-row lse + mean -------------------------------
__global__ void finalize_k(float* __restrict__ out) {
    float s = 0.f;
    for (int j = threadIdx.x; j < BN_; j += 1024) {
        float pos = g_pos[j];
        float tot = __expf(100.f * (pos - SHIFT)) + g_sum[0][j] + g_sum[1][j];
        s += logf(tot) + 100.f * SHIFT - 100.f * pos;
    }
    #pragma unroll
    for (int o = 16; o; o >>= 1) s += __shfl_xor_sync(0xffffffffu, s, o);
    __shared__ float red[32];
    int w = threadIdx.x >> 5, l = threadIdx.x & 31;
    if (l == 0) red[w] = s;
    __syncthreads();
    if (w == 0) {
        float t = red[l];
        #pragma unroll
        for (int o = 16; o; o >>= 1) t += __shfl_xor_sync(0xffffffffu, t, o);
        if (l == 0) out[0] = t * (1.0f / (float)BN_);
    }
}

// ---------------- launch ------------------------------------------------------
extern "C" void kernel_launch(void* const* d_in, const int* in_sizes, int n_in,
                              void* d_out, int out_size) {
    const float* feat     = (const float*)d_in[0];
    const float* feat_old = (const float*)d_in[1];
    const int*   tgt_raw  = (const int*)d_in[2];
    float* out = (float*)d_out;

    cudaFuncSetAttribute(gemm_mma_k, cudaFuncAttributeMaxDynamicSharedMemorySize,
                         GEMM_SMEM);

    prep_k<<<BN_ + 1, 128>>>(feat, feat_old, tgt_raw);
    dim3 grid(32, 32, 2);
    gemm_mma_k<<<grid, 512, GEMM_SMEM>>>();
    finalize_k<<<1, 1024>>>(out);
}

// round 16
// speedup vs baseline: 1.2111x; 1.0330x over previous
#include <cuda_runtime.h>
#include <cuda_fp16.h>
#include <math.h>
#include <stdint.h>

#define BN_ 4096
#define DN_ 512
#define KEFF 512
#define SHIFT 0.5f

// ---------------- scratch (device globals; allocation-free kernel_launch) ----
__device__ __half g_Ah[(size_t)BN_ * KEFF]; // fnh (4 MB)
__device__ __half g_Bo[(size_t)BN_ * KEFF]; // foh (4 MB)
__device__ float g_pos[BN_];
__device__ float g_sum[2][BN_];             // per-row sumexp (shifted)
__device__ int   g_tgt[BN_];

// ================= small PTX helpers (sm_100-safe) ===========================
__device__ __forceinline__ uint32_t smem_u32(const void* p) {
    uint32_t a;
    asm("{ .reg .u64 t; cvta.to.shared.u64 t, %1; cvt.u32.u64 %0, t; }"
        : "=r"(a) : "l"(p));
    return a;
}
__device__ __forceinline__ void cp16(uint32_t dst, const void* src) {
    asm volatile("cp.async.cg.shared.global [%0], [%1], 16;" :: "r"(dst), "l"(src));
}
#define CP_COMMIT() asm volatile("cp.async.commit_group;" ::: "memory")
#define CP_WAIT(n)  asm volatile("cp.async.wait_group %0;" :: "n"(n) : "memory")

__device__ __forceinline__ void ldsm_x4(uint32_t* r, uint32_t addr) {
    asm volatile("ldmatrix.sync.aligned.m8n8.x4.shared.b16 {%0,%1,%2,%3}, [%4];"
                 : "=r"(r[0]), "=r"(r[1]), "=r"(r[2]), "=r"(r[3]) : "r"(addr));
}
__device__ __forceinline__ void mma16816(float* c, const uint32_t* a, const uint32_t* b) {
    asm volatile(
        "mma.sync.aligned.m16n8k16.row.col.f32.f16.f16.f32 "
        "{%0,%1,%2,%3}, {%4,%5,%6,%7}, {%8,%9}, {%0,%1,%2,%3};"
        : "+f"(c[0]), "+f"(c[1]), "+f"(c[2]), "+f"(c[3])
        : "r"(a[0]), "r"(a[1]), "r"(a[2]), "r"(a[3]), "r"(b[0]), "r"(b[1]));
}

// ------- prep: warp-per-row (8 rows/block); block 512 handles targets --------
__global__ void __launch_bounds__(256) prep_k(const float* __restrict__ feat,
                                              const float* __restrict__ feat_old,
                                              const int* __restrict__ tgt_raw) {
    if (blockIdx.x == BN_ / 8) {
        // targets (int64/int32 autodetect) + zero accumulators
        __shared__ int s_any;
        if (threadIdx.x == 0) s_any = 0;
        __syncthreads();
        int local = 0;
        for (int j = threadIdx.x; j < BN_; j += 256)
            if ((j & 1) && tgt_raw[j] != 0) local = 1;
        if (local) atomicOr(&s_any, 1);
        __syncthreads();
        int is64 = (s_any == 0);
        for (int j = threadIdx.x; j < BN_; j += 256) {
            g_tgt[j] = is64 ? tgt_raw[2 * j] : tgt_raw[j];
            g_sum[0][j] = 0.f;
            g_sum[1][j] = 0.f;
        }
        return;
    }

    int warp = threadIdx.x >> 5, lane = threadIdx.x & 31;
    int row = blockIdx.x * 8 + warp;
    const float4* a4 = (const float4*)(feat + (size_t)row * DN_);
    const float4* b4 = (const float4*)(feat_old + (size_t)row * DN_);

    float4 av[4], bv[4];
    float snn = 0.f, soo = 0.f, sno = 0.f;
    #pragma unroll
    for (int q = 0; q < 4; q++) {
        av[q] = a4[lane + q * 32];
        bv[q] = b4[lane + q * 32];
        snn += av[q].x * av[q].x + av[q].y * av[q].y + av[q].z * av[q].z + av[q].w * av[q].w;
        soo += bv[q].x * bv[q].x + bv[q].y * bv[q].y + bv[q].z * bv[q].z + bv[q].w * bv[q].w;
        sno += av[q].x * bv[q].x + av[q].y * bv[q].y + av[q].z * bv[q].z + av[q].w * bv[q].w;
    }
    #pragma unroll
    for (int o = 16; o; o >>= 1) {
        snn += __shfl_xor_sync(0xffffffffu, snn, o);
        soo += __shfl_xor_sync(0xffffffffu, soo, o);
        sno += __shfl_xor_sync(0xffffffffu, sno, o);
    }
    float invn = 1.f / fmaxf(sqrtf(snn), 1e-12f);
    float invo = 1.f / fmaxf(sqrtf(soo), 1e-12f);
    if (lane == 0) g_pos[row] = sno * invn * invo;

    __half2* An = (__half2*)(g_Ah + (size_t)row * KEFF);
    __half2* Bo = (__half2*)(g_Bo + (size_t)row * KEFF);
    #pragma unroll
    for (int q = 0; q < 4; q++) {
        int base = (lane + q * 32) * 2;     // half2 index
        An[base + 0] = __floats2half2_rn(av[q].x * invn, av[q].y * invn);
        An[base + 1] = __floats2half2_rn(av[q].z * invn, av[q].w * invn);
        Bo[base + 0] = __floats2half2_rn(bv[q].x * invo, bv[q].y * invo);
        Bo[base + 1] = __floats2half2_rn(bv[q].z * invo, bv[q].w * invo);
    }
}

// == fp16 GEMM + masked exp row-sum; 512 thr, 32x32 warp tile, KC=64, 3-stage ==
#define KC 64
#define NITER (KEFF / KC)          // 8
#define ROWB 144                   // 128B data + 16B pad (conflict-free ldsm)
#define ATILE (128 * ROWB)         // 18432
#define STAGEB (2 * ATILE)         // 36864
#define GEMM_SMEM (3 * STAGEB)     // 110592

__global__ void __launch_bounds__(512, 2) gemm_mma_k() {
    int mat = blockIdx.z;
    int bx = blockIdx.x, by = blockIdx.y;
    if (mat == 1 && bx < by) return;          // symmetry: only upper triangle

    extern __shared__ char sm[];
    uint32_t sbase = smem_u32(sm);
    int tid = threadIdx.x, wid = tid >> 5, lane = tid & 31;
    int warpM = wid >> 2, warpN = wid & 3;    // 4x4 warps, 32x32 each
    const __half* Ag = g_Ah;
    const __half* Bg = mat ? g_Ah : g_Bo;
    int row0 = by * 128, col0 = bx * 128;

    // cp.async: 2048 segs/stage (16B each); 4 per thread
    uint32_t dseg[4];
    const char* pseg[4];
    #pragma unroll
    for (int k = 0; k < 4; k++) {
        int s = tid + k * 512;
        int isB = s >= 1024;
        int r = (s - (isB ? 1024 : 0)) >> 3;
        int sc = s & 7;
        const __half* base = isB ? Bg : Ag;
        int gr = (isB ? col0 : row0) + r;
        pseg[k] = (const char*)(base + (size_t)gr * KEFF) + sc * 16;
        dseg[k] = (isB ? ATILE : 0) + r * ROWB + sc * 16;
    }

    #define ISSUE(it) do {                                                     \
        uint32_t st = sbase + ((it) % 3) * STAGEB;                             \
        int ko = (it) * 128;                                                   \
        cp16(st + dseg[0], pseg[0] + ko); cp16(st + dseg[1], pseg[1] + ko);    \
        cp16(st + dseg[2], pseg[2] + ko); cp16(st + dseg[3], pseg[3] + ko);    \
    } while (0)

    ISSUE(0); CP_COMMIT();
    ISSUE(1); CP_COMMIT();

    float acc[2][4][4] = {};
    uint32_t aoff = (uint32_t)((warpM * 32 + (lane & 15)) * ROWB + (lane >> 4) * 16);
    uint32_t boff = (uint32_t)(ATILE +
        (warpN * 32 + (lane & 7) + (lane >> 4) * 8) * ROWB + ((lane >> 3) & 1) * 16);

    for (int it = 0; it < NITER; it++) {
        CP_WAIT(1);
        __syncthreads();
        if (it + 2 < NITER) ISSUE(it + 2);
        CP_COMMIT();

        uint32_t st = sbase + (it % 3) * STAGEB;
        uint32_t ab = st + aoff, bb = st + boff;
        #pragma unroll
        for (int kk = 0; kk < 4; kk++) {
            uint32_t af[2][4], bf[2][4];
            ldsm_x4(af[0], ab + kk * 32);
            ldsm_x4(af[1], ab + kk * 32 + 16 * ROWB);
            ldsm_x4(bf[0], bb + kk * 32);
            ldsm_x4(bf[1], bb + kk * 32 + 16 * ROWB);
            #pragma unroll
            for (int mt = 0; mt < 2; mt++)
                #pragma unroll
                for (int nt = 0; nt < 4; nt++)
                    mma16816(acc[mt][nt], af[mt], &bf[nt >> 1][(nt & 1) * 2]);
        }
    }

    CP_WAIT(0);
    __syncthreads();

    // ---- epilogue: masked exp, accumulate row (and sym col) sums ----
    float* srow = (float*)sm;                 // [128]
    float* scol = (float*)(sm + 512);         // [128]
    int* tjs = (int*)(sm + 1024);             // [128]
    if (tid < 128) {
        srow[tid] = 0.f;
        scol[tid] = 0.f;
        tjs[tid] = g_tgt[col0 + tid];
    }
    __syncthreads();

    bool sym = (mat == 1) && (bx > by);

    #pragma unroll
    for (int mt = 0; mt < 2; mt++) {
        int rl0 = warpM * 32 + mt * 16 + (lane >> 2);
        int ti0 = g_tgt[row0 + rl0], ti1 = g_tgt[row0 + rl0 + 8];
        #pragma unroll
        for (int nt = 0; nt < 4; nt++) {
            int cl = warpN * 32 + nt * 8 + (lane & 3) * 2;
            int tj0 = tjs[cl], tj1 = tjs[cl + 1];
            acc[mt][nt][0] = (ti0 == tj0) ? 0.f : __expf(100.f * (acc[mt][nt][0] - SHIFT));
            acc[mt][nt][1] = (ti0 == tj1) ? 0.f : __expf(100.f * (acc[mt][nt][1] - SHIFT));
            acc[mt][nt][2] = (ti1 == tj0) ? 0.f : __expf(100.f * (acc[mt][nt][2] - SHIFT));
            acc[mt][nt][3] = (ti1 == tj1) ? 0.f : __expf(100.f * (acc[mt][nt][3] - SHIFT));
        }
        float s0 = 0.f, s1 = 0.f;
        #pragma unroll
        for (int nt = 0; nt < 4; nt++) {
            s0 += acc[mt][nt][0] + acc[mt][nt][1];
            s1 += acc[mt][nt][2] + acc[mt][nt][3];
        }
        atomicAdd(&srow[rl0], s0);
        atomicAdd(&srow[rl0 + 8], s1);
    }
    if (sym) {
        #pragma unroll
        for (int nt = 0; nt < 4; nt++) {
            int cl = warpN * 32 + nt * 8 + (lane & 3) * 2;
            float c0 = 0.f, c1 = 0.f;
            #pragma unroll
            for (int mt = 0; mt < 2; mt++) {
                c0 += acc[mt][nt][0] + acc[mt][nt][2];
                c1 += acc[mt][nt][1] + acc[mt][nt][3];
            }
            atomicAdd(&scol[cl], c0);
            atomicAdd(&scol[cl + 1], c1);
        }
    }
    __syncthreads();

    if (tid < 128) {
        atomicAdd(&g_sum[mat][row0 + tid], srow[tid]);
        if (sym) atomicAdd(&g_sum[1][col0 + tid], scol[tid]);
    }
    #undef ISSUE
}

// ---------------- finalize: per-row lse + mean -------------------------------
__global__ void finalize_k(float* __restrict__ out) {
    float s = 0.f;
    for (int j = threadIdx.x; j < BN_; j += 1024) {
        float pos = g_pos[j];
        float tot = __expf(100.f * (pos - SHIFT)) + g_sum[0][j] + g_sum[1][j];
        s += logf(tot) + 100.f * SHIFT - 100.f * pos;
    }
    #pragma unroll
    for (int o = 16; o; o >>= 1) s += __shfl_xor_sync(0xffffffffu, s, o);
    __shared__ float red[32];
    int w = threadIdx.x >> 5, l = threadIdx.x & 31;
    if (l == 0) red[w] = s;
    __syncthreads();
    if (w == 0) {
        float t = red[l];
        #pragma unroll
        for (int o = 16; o; o >>= 1) t += __shfl_xor_sync(0xffffffffu, t, o);
        if (l == 0) out[0] = t * (1.0f / (float)BN_);
    }
}

// ---------------- launch ------------------------------------------------------
extern "C" void kernel_launch(void* const* d_in, const int* in_sizes, int n_in,
                              void* d_out, int out_size) {
    const float* feat     = (const float*)d_in[0];
    const float* feat_old = (const float*)d_in[1];
    const int*   tgt_raw  = (const int*)d_in[2];
    float* out = (float*)d_out;

    cudaFuncSetAttribute(gemm_mma_k, cudaFuncAttributeMaxDynamicSharedMemorySize,
                         GEMM_SMEM);

    prep_k<<<BN_ / 8 + 1, 256>>>(feat, feat_old, tgt_raw);
    dim3 grid(32, 32, 2);
    gemm_mma_k<<<grid, 512, GEMM_SMEM>>>();
    finalize_k<<<1, 1024>>>(out);
}

// round 17
// speedup vs baseline: 1.2293x; 1.0150x over previous
#include <cuda_runtime.h>
#include <cuda_fp16.h>
#include <math.h>
#include <stdint.h>

#define BN_ 4096
#define DN_ 512
#define KEFF 512
#define SHIFT 0.5f

// ---------------- scratch (device globals; allocation-free kernel_launch) ----
__device__ __half g_Ah[(size_t)BN_ * KEFF]; // fnh (4 MB)
__device__ __half g_Bo[(size_t)BN_ * KEFF]; // foh (4 MB)
__device__ float g_pos[BN_];
__device__ float g_sum[2][BN_];             // per-row sumexp (shifted)
__device__ int   g_tgt[BN_];

// ================= small PTX helpers (sm_100-safe) ===========================
__device__ __forceinline__ uint32_t smem_u32(const void* p) {
    uint32_t a;
    asm("{ .reg .u64 t; cvta.to.shared.u64 t, %1; cvt.u32.u64 %0, t; }"
        : "=r"(a) : "l"(p));
    return a;
}
__device__ __forceinline__ void cp16(uint32_t dst, const void* src) {
    asm volatile("cp.async.cg.shared.global [%0], [%1], 16;" :: "r"(dst), "l"(src));
}
#define CP_COMMIT() asm volatile("cp.async.commit_group;" ::: "memory")
#define CP_WAIT(n)  asm volatile("cp.async.wait_group %0;" :: "n"(n) : "memory")

__device__ __forceinline__ void ldsm_x4(uint32_t* r, uint32_t addr) {
    asm volatile("ldmatrix.sync.aligned.m8n8.x4.shared.b16 {%0,%1,%2,%3}, [%4];"
                 : "=r"(r[0]), "=r"(r[1]), "=r"(r[2]), "=r"(r[3]) : "r"(addr));
}
__device__ __forceinline__ void mma16816(float* c, const uint32_t* a, const uint32_t* b) {
    asm volatile(
        "mma.sync.aligned.m16n8k16.row.col.f32.f16.f16.f32 "
        "{%0,%1,%2,%3}, {%4,%5,%6,%7}, {%8,%9}, {%0,%1,%2,%3};"
        : "+f"(c[0]), "+f"(c[1]), "+f"(c[2]), "+f"(c[3])
        : "r"(a[0]), "r"(a[1]), "r"(a[2]), "r"(a[3]), "r"(b[0]), "r"(b[1]));
}

// ---- prep: half-row per warp (4 rows/block, 8 warps); last block: targets ---
__global__ void __launch_bounds__(256) prep_k(const float* __restrict__ feat,
                                              const float* __restrict__ feat_old,
                                              const int* __restrict__ tgt_raw,
                                              float* __restrict__ out) {
    if (blockIdx.x == BN_ / 4) {
        // targets (int64/int32 autodetect) + zero accumulators + out
        __shared__ int s_any;
        if (threadIdx.x == 0) { s_any = 0; out[0] = 0.f; }
        __syncthreads();
        int local = 0;
        for (int j = threadIdx.x; j < BN_; j += 256)
            if ((j & 1) && tgt_raw[j] != 0) local = 1;
        if (local) atomicOr(&s_any, 1);
        __syncthreads();
        int is64 = (s_any == 0);
        for (int j = threadIdx.x; j < BN_; j += 256) {
            g_tgt[j] = is64 ? tgt_raw[2 * j] : tgt_raw[j];
            g_sum[0][j] = 0.f;
            g_sum[1][j] = 0.f;
        }
        return;
    }

    __shared__ float part[3][8];
    int warp = threadIdx.x >> 5, lane = threadIdx.x & 31;
    int row = blockIdx.x * 4 + (warp >> 1);
    int half = warp & 1;
    const float4* a4 = (const float4*)(feat + (size_t)row * DN_);
    const float4* b4 = (const float4*)(feat_old + (size_t)row * DN_);

    float4 av[2], bv[2];
    float snn = 0.f, soo = 0.f, sno = 0.f;
    #pragma unroll
    for (int q = 0; q < 2; q++) {
        int f4 = half * 64 + q * 32 + lane;
        av[q] = a4[f4];
        bv[q] = b4[f4];
        snn += av[q].x * av[q].x + av[q].y * av[q].y + av[q].z * av[q].z + av[q].w * av[q].w;
        soo += bv[q].x * bv[q].x + bv[q].y * bv[q].y + bv[q].z * bv[q].z + bv[q].w * bv[q].w;
        sno += av[q].x * bv[q].x + av[q].y * bv[q].y + av[q].z * bv[q].z + av[q].w * bv[q].w;
    }
    #pragma unroll
    for (int o = 16; o; o >>= 1) {
        snn += __shfl_xor_sync(0xffffffffu, snn, o);
        soo += __shfl_xor_sync(0xffffffffu, soo, o);
        sno += __shfl_xor_sync(0xffffffffu, sno, o);
    }
    if (lane == 0) { part[0][warp] = snn; part[1][warp] = soo; part[2][warp] = sno; }
    __syncthreads();
    float tn = part[0][warp] + part[0][warp ^ 1];
    float to = part[1][warp] + part[1][warp ^ 1];
    float tx = part[2][warp] + part[2][warp ^ 1];
    float invn = 1.f / fmaxf(sqrtf(tn), 1e-12f);
    float invo = 1.f / fmaxf(sqrtf(to), 1e-12f);
    if (lane == 0 && half == 0) g_pos[row] = tx * invn * invo;

    __half2* An = (__half2*)(g_Ah + (size_t)row * KEFF);
    __half2* Bo = (__half2*)(g_Bo + (size_t)row * KEFF);
    #pragma unroll
    for (int q = 0; q < 2; q++) {
        int f4 = half * 64 + q * 32 + lane;
        An[f4 * 2 + 0] = __floats2half2_rn(av[q].x * invn, av[q].y * invn);
        An[f4 * 2 + 1] = __floats2half2_rn(av[q].z * invn, av[q].w * invn);
        Bo[f4 * 2 + 0] = __floats2half2_rn(bv[q].x * invo, bv[q].y * invo);
        Bo[f4 * 2 + 1] = __floats2half2_rn(bv[q].z * invo, bv[q].w * invo);
    }
}

// == fp16 GEMM + masked exp row-sum; 512 thr, 32x32 warp tile, KC=64, 3-stage ==
#define KC 64
#define NITER (KEFF / KC)          // 8
#define ROWB 144                   // 128B data + 16B pad (conflict-free ldsm)
#define ATILE (128 * ROWB)         // 18432
#define STAGEB (2 * ATILE)         // 36864
#define GEMM_SMEM (3 * STAGEB)     // 110592

__global__ void __launch_bounds__(512, 2) gemm_mma_k() {
    int mat = blockIdx.z;
    int bx = blockIdx.x, by = blockIdx.y;
    if (mat == 1 && bx < by) return;          // symmetry: only upper triangle

    extern __shared__ char sm[];
    uint32_t sbase = smem_u32(sm);
    int tid = threadIdx.x, wid = tid >> 5, lane = tid & 31;
    int warpM = wid >> 2, warpN = wid & 3;    // 4x4 warps, 32x32 each
    const __half* Ag = g_Ah;
    const __half* Bg = mat ? g_Ah : g_Bo;
    int row0 = by * 128, col0 = bx * 128;

    // cp.async: 2048 segs/stage (16B each); 4 per thread
    uint32_t dseg[4];
    const char* pseg[4];
    #pragma unroll
    for (int k = 0; k < 4; k++) {
        int s = tid + k * 512;
        int isB = s >= 1024;
        int r = (s - (isB ? 1024 : 0)) >> 3;
        int sc = s & 7;
        const __half* base = isB ? Bg : Ag;
        int gr = (isB ? col0 : row0) + r;
        pseg[k] = (const char*)(base + (size_t)gr * KEFF) + sc * 16;
        dseg[k] = (isB ? ATILE : 0) + r * ROWB + sc * 16;
    }

    #define ISSUE(it) do {                                                     \
        uint32_t st = sbase + ((it) % 3) * STAGEB;                             \
        int ko = (it) * 128;                                                   \
        cp16(st + dseg[0], pseg[0] + ko); cp16(st + dseg[1], pseg[1] + ko);    \
        cp16(st + dseg[2], pseg[2] + ko); cp16(st + dseg[3], pseg[3] + ko);    \
    } while (0)

    ISSUE(0); CP_COMMIT();
    ISSUE(1); CP_COMMIT();

    float acc[2][4][4] = {};
    uint32_t aoff = (uint32_t)((warpM * 32 + (lane & 15)) * ROWB + (lane >> 4) * 16);
    uint32_t boff = (uint32_t)(ATILE +
        (warpN * 32 + (lane & 7) + (lane >> 4) * 8) * ROWB + ((lane >> 3) & 1) * 16);

    for (int it = 0; it < NITER; it++) {
        CP_WAIT(1);
        __syncthreads();
        if (it + 2 < NITER) ISSUE(it + 2);
        CP_COMMIT();

        uint32_t st = sbase + (it % 3) * STAGEB;
        uint32_t ab = st + aoff, bb = st + boff;
        #pragma unroll
        for (int kk = 0; kk < 4; kk++) {
            uint32_t af[2][4], bf[2][4];
            ldsm_x4(af[0], ab + kk * 32);
            ldsm_x4(af[1], ab + kk * 32 + 16 * ROWB);
            ldsm_x4(bf[0], bb + kk * 32);
            ldsm_x4(bf[1], bb + kk * 32 + 16 * ROWB);
            #pragma unroll
            for (int mt = 0; mt < 2; mt++)
                #pragma unroll
                for (int nt = 0; nt < 4; nt++)
                    mma16816(acc[mt][nt], af[mt], &bf[nt >> 1][(nt & 1) * 2]);
        }
    }

    CP_WAIT(0);
    __syncthreads();

    // ---- epilogue: masked exp, accumulate row (and sym col) sums ----
    float* srow = (float*)sm;                 // [128]
    float* scol = (float*)(sm + 512);         // [128]
    int* tjs = (int*)(sm + 1024);             // [128]
    if (tid < 128) {
        srow[tid] = 0.f;
        scol[tid] = 0.f;
        tjs[tid] = g_tgt[col0 + tid];
    }
    __syncthreads();

    bool sym = (mat == 1) && (bx > by);

    #pragma unroll
    for (int mt = 0; mt < 2; mt++) {
        int rl0 = warpM * 32 + mt * 16 + (lane >> 2);
        int ti0 = g_tgt[row0 + rl0], ti1 = g_tgt[row0 + rl0 + 8];
        #pragma unroll
        for (int nt = 0; nt < 4; nt++) {
            int cl = warpN * 32 + nt * 8 + (lane & 3) * 2;
            int tj0 = tjs[cl], tj1 = tjs[cl + 1];
            acc[mt][nt][0] = (ti0 == tj0) ? 0.f : __expf(100.f * (acc[mt][nt][0] - SHIFT));
            acc[mt][nt][1] = (ti0 == tj1) ? 0.f : __expf(100.f * (acc[mt][nt][1] - SHIFT));
            acc[mt][nt][2] = (ti1 == tj0) ? 0.f : __expf(100.f * (acc[mt][nt][2] - SHIFT));
            acc[mt][nt][3] = (ti1 == tj1) ? 0.f : __expf(100.f * (acc[mt][nt][3] - SHIFT));
        }
        float s0 = 0.f, s1 = 0.f;
        #pragma unroll
        for (int nt = 0; nt < 4; nt++) {
            s0 += acc[mt][nt][0] + acc[mt][nt][1];
            s1 += acc[mt][nt][2] + acc[mt][nt][3];
        }
        atomicAdd(&srow[rl0], s0);
        atomicAdd(&srow[rl0 + 8], s1);
    }
    if (sym) {
        #pragma unroll
        for (int nt = 0; nt < 4; nt++) {
            int cl = warpN * 32 + nt * 8 + (lane & 3) * 2;
            float c0 = 0.f, c1 = 0.f;
            #pragma unroll
            for (int mt = 0; mt < 2; mt++) {
                c0 += acc[mt][nt][0] + acc[mt][nt][2];
                c1 += acc[mt][nt][1] + acc[mt][nt][3];
            }
            atomicAdd(&scol[cl], c0);
            atomicAdd(&scol[cl + 1], c1);
        }
    }
    __syncthreads();

    if (tid < 128) {
        atomicAdd(&g_sum[mat][row0 + tid], srow[tid]);
        if (sym) atomicAdd(&g_sum[1][col0 + tid], scol[tid]);
    }
    #undef ISSUE
}

// ------- finalize: 16 blocks, one row/thread, atomic partial into out --------
__global__ void __launch_bounds__(256) finalize_k(float* __restrict__ out) {
    int j = blockIdx.x * 256 + threadIdx.x;
    float pos = g_pos[j];
    float tot = __expf(100.f * (pos - SHIFT)) + g_sum[0][j] + g_sum[1][j];
    float s = logf(tot) + 100.f * SHIFT - 100.f * pos;

    #pragma unroll
    for (int o = 16; o; o >>= 1) s += __shfl_xor_sync(0xffffffffu, s, o);
    __shared__ float red[8];
    int w = threadIdx.x >> 5, l = threadIdx.x & 31;
    if (l == 0) red[w] = s;
    __syncthreads();
    if (threadIdx.x == 0) {
        float t = 0.f;
        #pragma unroll
        for (int q = 0; q < 8; q++) t += red[q];
        atomicAdd(out, t * (1.0f / (float)BN_));
    }
}

// ---------------- launch ------------------------------------------------------
extern "C" void kernel_launch(void* const* d_in, const int* in_sizes, int n_in,
                              void* d_out, int out_size) {
    const float* feat     = (const float*)d_in[0];
    const float* feat_old = (const float*)d_in[1];
    const int*   tgt_raw  = (const int*)d_in[2];
    float* out = (float*)d_out;

    cudaFuncSetAttribute(gemm_mma_k, cudaFuncAttributeMaxDynamicSharedMemorySize,
                         GEMM_SMEM);

    prep_k<<<BN_ / 4 + 1, 256>>>(feat, feat_old, tgt_raw, out);
    dim3 grid(32, 32, 2);
    gemm_mma_k<<<grid, 512, GEMM_SMEM>>>();
    finalize_k<<<BN_ / 256, 256>>>(out);
}